// round 11
// baseline (speedup 1.0000x reference)
#include <cuda_runtime.h>

#define DIM     128
#define NHEADS  4
#define HD      32
#define MAXN    100000
#define TB      128     // GEMM row-tile
#define XPAD    132     // padded X tile row stride (floats)

// Scratch (allocation-free rule: __device__ globals)
__device__ float g_q[(size_t)MAXN * DIM];
__device__ float g_k[(size_t)MAXN * DIM];
__device__ float g_v[(size_t)MAXN * DIM];
__device__ float g_agg[(size_t)MAXN * DIM];

static const int GEMM_SMEM = (TB * XPAD + DIM * DIM) * 4;  // 133120 B

typedef unsigned long long ull;

// ---------- packed fp32x2 helpers (FFMA2 path, sm_100+) ----------
__device__ __forceinline__ ull pack2(float lo, float hi) {
    ull r;
    asm("mov.b64 %0, {%1, %2};" : "=l"(r) : "f"(lo), "f"(hi));
    return r;
}
__device__ __forceinline__ void fma2(ull& d, ull a, ull b) {
    asm("fma.rn.f32x2 %0, %1, %2, %3;" : "=l"(d) : "l"(a), "l"(b), "l"(d));
}
__device__ __forceinline__ float2 unpack2(ull v) {
    float2 r;
    asm("mov.b64 {%0, %1}, %2;" : "=f"(r.x), "=f"(r.y) : "l"(v));
    return r;
}

// ============================================================================
// Generic 128-wide GEMM: O[r,:] = X[r,:] @ W + b  (+ resid[r,:] if RESID)
// 512 threads, 128x128 tile, 4 rows x 8 cols per thread (4x4 f32x2 acc).
// ============================================================================
template <bool RESID>
__global__ void __launch_bounds__(512, 1) gemm128(
    const float* __restrict__ X, const float* __restrict__ W,
    const float* __restrict__ b, const float* __restrict__ resid,
    float* __restrict__ O, int N)
{
    extern __shared__ float sm[];
    float* Xs = sm;                // [TB][XPAD]
    float* Ws = sm + TB * XPAD;    // [128][128] k-major
    const int tid  = threadIdx.x;
    const int row0 = blockIdx.x * TB;

    // Cooperative load: X tile (zero-fill OOB) + full W. 8 float4 each.
    {
        const int c4 = tid & 31;
        const int r0 = tid >> 5;   // 0..15
        const float4* Wsrc = (const float4*)W;
        #pragma unroll
        for (int i = 0; i < 8; i++) {
            int row  = r0 + i * 16;
            int grow = row0 + row;
            float4 v = make_float4(0.f, 0.f, 0.f, 0.f);
            if (grow < N) v = ((const float4*)(X + (size_t)grow * DIM))[c4];
            float* d = Xs + row * XPAD + c4 * 4;
            d[0] = v.x; d[1] = v.y; d[2] = v.z; d[3] = v.w;
            ((float4*)(Ws + row * DIM))[c4] = Wsrc[row * 32 + c4];
        }
    }
    __syncthreads();

    const int tx = tid & 15;   // cols [tx*8, tx*8+8)
    const int ty = tid >> 4;   // rows [ty*4, ty*4+4)

    ull acc[4][4];
    {
        const float* bb = b + tx * 8;
        #pragma unroll
        for (int j = 0; j < 4; j++) {
            ull bv2 = pack2(bb[2 * j], bb[2 * j + 1]);
            #pragma unroll
            for (int i = 0; i < 4; i++) acc[i][j] = bv2;
        }
    }

    const float* arow0 = Xs + (ty * 4) * XPAD;

    #pragma unroll 4
    for (int k = 0; k < DIM; k++) {
        const float4* brow = (const float4*)(Ws + k * DIM + tx * 8);
        float4 bA = brow[0], bB = brow[1];
        ull B[4];
        B[0] = pack2(bA.x, bA.y); B[1] = pack2(bA.z, bA.w);
        B[2] = pack2(bB.x, bB.y); B[3] = pack2(bB.z, bB.w);
        #pragma unroll
        for (int i = 0; i < 4; i++) {
            float a = arow0[i * XPAD + k];
            ull a2 = pack2(a, a);
            #pragma unroll
            for (int j = 0; j < 4; j++) fma2(acc[i][j], a2, B[j]);
        }
    }

    #pragma unroll
    for (int i = 0; i < 4; i++) {
        int grow = row0 + ty * 4 + i;
        if (grow < N) {
            float2 p0 = unpack2(acc[i][0]), p1 = unpack2(acc[i][1]);
            float2 p2 = unpack2(acc[i][2]), p3 = unpack2(acc[i][3]);
            float4 o0 = make_float4(p0.x, p0.y, p1.x, p1.y);
            float4 o1 = make_float4(p2.x, p2.y, p3.x, p3.y);
            if (RESID) {
                const float4* res = (const float4*)(resid + (size_t)grow * DIM + tx * 8);
                float4 r0v = res[0], r1v = res[1];
                o0.x += r0v.x; o0.y += r0v.y; o0.z += r0v.z; o0.w += r0v.w;
                o1.x += r1v.x; o1.y += r1v.y; o1.z += r1v.z; o1.w += r1v.w;
            }
            float4* dst = (float4*)(O + (size_t)grow * DIM + tx * 8);
            dst[0] = o0;
            dst[1] = o1;
        }
    }
}

// ============================================================================
// Edge attention + scatter. One warp per edge; lane owns 4 contiguous dims
// (head = lane>>3). Softmax is over the 4 HEADS (faithful to reference).
// Scatter via red.global.add.v4.f32 (4x fewer L2 atomic ops than scalar).
// ============================================================================
__global__ void edge_attn(const int* __restrict__ senders,
                          const int* __restrict__ receivers, int E)
{
    int gw = (blockIdx.x * blockDim.x + threadIdx.x) >> 5;
    if (gw >= E) return;          // uniform per warp
    const int lane = threadIdx.x & 31;
    const int s = senders[gw];
    const int r = receivers[gw];

    float4 q  = ((const float4*)g_q)[s * 32 + lane];
    float4 kk = ((const float4*)g_k)[r * 32 + lane];
    float p = q.x * kk.x + q.y * kk.y + q.z * kk.z + q.w * kk.w;
    // reduce within each 8-lane head group
    p += __shfl_xor_sync(0xffffffffu, p, 4);
    p += __shfl_xor_sync(0xffffffffu, p, 2);
    p += __shfl_xor_sync(0xffffffffu, p, 1);

    const float inv_sqrt_hd = 0.17677669529663687f;  // 1/sqrt(32)
    float s0 = __shfl_sync(0xffffffffu, p, 0)  * inv_sqrt_hd;
    float s1 = __shfl_sync(0xffffffffu, p, 8)  * inv_sqrt_hd;
    float s2 = __shfl_sync(0xffffffffu, p, 16) * inv_sqrt_hd;
    float s3 = __shfl_sync(0xffffffffu, p, 24) * inv_sqrt_hd;

    float m  = fmaxf(fmaxf(s0, s1), fmaxf(s2, s3));
    float e0 = __expf(s0 - m), e1 = __expf(s1 - m);
    float e2 = __expf(s2 - m), e3 = __expf(s3 - m);
    float inv_sum = 1.0f / (e0 + e1 + e2 + e3);
    float eh = (lane & 16) ? ((lane & 8) ? e3 : e2)
                           : ((lane & 8) ? e1 : e0);
    float attn = eh * inv_sum;

    float4 v = ((const float4*)g_v)[s * 32 + lane];
    float* dst = g_agg + (size_t)r * DIM + lane * 4;
    asm volatile("red.global.add.v4.f32 [%0], {%1, %2, %3, %4};"
                 :: "l"(dst), "f"(v.x * attn), "f"(v.y * attn),
                    "f"(v.z * attn), "f"(v.w * attn)
                 : "memory");
}

__global__ void zero_agg_kernel(int n4) {
    int i = blockIdx.x * blockDim.x + threadIdx.x;
    if (i < n4) ((float4*)g_agg)[i] = make_float4(0.f, 0.f, 0.f, 0.f);
}

// ============================================================================
extern "C" void kernel_launch(void* const* d_in, const int* in_sizes, int n_in,
                              void* d_out, int out_size)
{
    const float* nodes     = (const float*)d_in[0];
    const int*   senders   = (const int*)  d_in[1];
    const int*   receivers = (const int*)  d_in[2];
    const float* Wq = (const float*)d_in[3];
    const float* bq = (const float*)d_in[4];
    const float* Wk = (const float*)d_in[5];
    const float* bk = (const float*)d_in[6];
    const float* Wv = (const float*)d_in[7];
    const float* bv = (const float*)d_in[8];
    const float* Wo = (const float*)d_in[9];
    const float* bo = (const float*)d_in[10];

    int N = in_sizes[0] / DIM;
    int E = in_sizes[1];

    float *qp, *kp, *vp, *aggp;
    cudaGetSymbolAddress((void**)&qp,   g_q);
    cudaGetSymbolAddress((void**)&kp,   g_k);
    cudaGetSymbolAddress((void**)&vp,   g_v);
    cudaGetSymbolAddress((void**)&aggp, g_agg);

    cudaFuncSetAttribute(gemm128<false>, cudaFuncAttributeMaxDynamicSharedMemorySize, GEMM_SMEM);
    cudaFuncSetAttribute(gemm128<true>,  cudaFuncAttributeMaxDynamicSharedMemorySize, GEMM_SMEM);

    int gemm_blocks = (N + TB - 1) / TB;
    int n4 = N * (DIM / 4);

    zero_agg_kernel<<<(n4 + 255) / 256, 256>>>(n4);
    gemm128<false><<<gemm_blocks, 512, GEMM_SMEM>>>(nodes, Wq, bq, nullptr, qp, N);
    gemm128<false><<<gemm_blocks, 512, GEMM_SMEM>>>(nodes, Wk, bk, nullptr, kp, N);
    gemm128<false><<<gemm_blocks, 512, GEMM_SMEM>>>(nodes, Wv, bv, nullptr, vp, N);
    edge_attn<<<(E + 7) / 8, 256>>>(senders, receivers, E);
    gemm128<true><<<gemm_blocks, 512, GEMM_SMEM>>>(aggp, Wo, bo, nodes, (float*)d_out, N);
}